// round 1
// baseline (speedup 1.0000x reference)
#include <cuda_runtime.h>

#define NODES 40000
#define EDGES 640000
#define DIM 128
#define GRAPHS 512
#define NEG_SLOPE 0.2f
#define BN_EPS 1e-5f

// ---------------- scratch (no allocations allowed) ----------------
__device__ float d_h0[NODES * DIM];
__device__ float d_h1[NODES * DIM];
__device__ float d_xl[NODES * DIM];
__device__ float d_xr[NODES * DIM];
__device__ int d_deg[NODES];
__device__ int d_rowptr[NODES + 1];
__device__ int d_cursor[NODES];
__device__ int d_srcs[EDGES];

// ---------------- CSR build (once per call, reused by all 3 layers) ----------------
__global__ void k_zero_deg() {
    int i = blockIdx.x * blockDim.x + threadIdx.x;
    if (i < NODES) d_deg[i] = 0;
}

__global__ void k_hist(const int* __restrict__ ei) {
    int e = blockIdx.x * blockDim.x + threadIdx.x;
    if (e < EDGES) atomicAdd(&d_deg[ei[EDGES + e]], 1);
}

__global__ void k_scan() {
    __shared__ int ws[32];
    __shared__ int s_carry;
    __shared__ int s_total;
    int tid = threadIdx.x;
    int lane = tid & 31;
    int wid = tid >> 5;
    if (tid == 0) s_carry = 0;
    __syncthreads();
    for (int base = 0; base < NODES; base += 1024) {
        int i = base + tid;
        int v = (i < NODES) ? d_deg[i] : 0;
        int x = v;
        #pragma unroll
        for (int o = 1; o < 32; o <<= 1) {
            int y = __shfl_up_sync(0xffffffffu, x, o);
            if (lane >= o) x += y;
        }
        if (lane == 31) ws[wid] = x;
        __syncthreads();
        if (wid == 0) {
            int sv = ws[lane];
            int sx = sv;
            #pragma unroll
            for (int o = 1; o < 32; o <<= 1) {
                int y = __shfl_up_sync(0xffffffffu, sx, o);
                if (lane >= o) sx += y;
            }
            ws[lane] = sx - sv;              // exclusive warp-sum prefix
            if (lane == 31) s_total = sx;    // chunk total
        }
        __syncthreads();
        int excl = s_carry + ws[wid] + x - v;
        if (i < NODES) { d_rowptr[i] = excl; d_cursor[i] = excl; }
        __syncthreads();
        if (tid == 0) s_carry += s_total;
        __syncthreads();
    }
    if (threadIdx.x == 0) d_rowptr[NODES] = s_carry;
}

__global__ void k_scatter(const int* __restrict__ ei) {
    int e = blockIdx.x * blockDim.x + threadIdx.x;
    if (e < EDGES) {
        int dst = ei[EDGES + e];
        int pos = atomicAdd(&d_cursor[dst], 1);
        d_srcs[pos] = ei[e];
    }
}

// ---------------- dual GEMM: xl = X@Wl + bl, xr = X@Wr + br ----------------
// 64-row tile per block, 256 threads; thread -> 2 rows x 16 cols x 2 matrices.
__global__ __launch_bounds__(256, 2) void k_gemm_dual(
    const float* __restrict__ X,
    const float* __restrict__ Wl, const float* __restrict__ bl,
    const float* __restrict__ Wr, const float* __restrict__ br,
    float* __restrict__ xl, float* __restrict__ xr)
{
    __shared__ float xs[64][DIM + 1];  // +1 pad: conflict-free broadcast reads
    int tid = threadIdx.x;
    int row0 = blockIdx.x * 64;
    for (int t = tid; t < 64 * DIM; t += 256)
        xs[t >> 7][t & 127] = X[(size_t)row0 * DIM + t];
    __syncthreads();

    int g = tid & 7;        // col group (8 groups of 16 cols)
    int r0 = tid >> 3;      // 0..31
    int r1 = r0 + 32;
    int col = g * 16;
    int g4 = g * 4;

    float aL0[16], aL1[16], aR0[16], aR1[16];
    #pragma unroll
    for (int j = 0; j < 16; j++) { aL0[j] = 0.f; aL1[j] = 0.f; aR0[j] = 0.f; aR1[j] = 0.f; }

    const float4* WlV = (const float4*)Wl;
    const float4* WrV = (const float4*)Wr;

    #pragma unroll 2
    for (int k = 0; k < DIM; k++) {
        float x0 = xs[r0][k];
        float x1 = xs[r1][k];
        #pragma unroll
        for (int j = 0; j < 4; j++) {
            float4 wl4 = WlV[k * 32 + g4 + j];
            float4 wr4 = WrV[k * 32 + g4 + j];
            aL0[4 * j + 0] = fmaf(x0, wl4.x, aL0[4 * j + 0]);
            aL0[4 * j + 1] = fmaf(x0, wl4.y, aL0[4 * j + 1]);
            aL0[4 * j + 2] = fmaf(x0, wl4.z, aL0[4 * j + 2]);
            aL0[4 * j + 3] = fmaf(x0, wl4.w, aL0[4 * j + 3]);
            aL1[4 * j + 0] = fmaf(x1, wl4.x, aL1[4 * j + 0]);
            aL1[4 * j + 1] = fmaf(x1, wl4.y, aL1[4 * j + 1]);
            aL1[4 * j + 2] = fmaf(x1, wl4.z, aL1[4 * j + 2]);
            aL1[4 * j + 3] = fmaf(x1, wl4.w, aL1[4 * j + 3]);
            aR0[4 * j + 0] = fmaf(x0, wr4.x, aR0[4 * j + 0]);
            aR0[4 * j + 1] = fmaf(x0, wr4.y, aR0[4 * j + 1]);
            aR0[4 * j + 2] = fmaf(x0, wr4.z, aR0[4 * j + 2]);
            aR0[4 * j + 3] = fmaf(x0, wr4.w, aR0[4 * j + 3]);
            aR1[4 * j + 0] = fmaf(x1, wr4.x, aR1[4 * j + 0]);
            aR1[4 * j + 1] = fmaf(x1, wr4.y, aR1[4 * j + 1]);
            aR1[4 * j + 2] = fmaf(x1, wr4.z, aR1[4 * j + 2]);
            aR1[4 * j + 3] = fmaf(x1, wr4.w, aR1[4 * j + 3]);
        }
    }

    const float4* blv = (const float4*)(bl + col);
    const float4* brv = (const float4*)(br + col);
    float4* xl0 = (float4*)(xl + (size_t)(row0 + r0) * DIM + col);
    float4* xl1 = (float4*)(xl + (size_t)(row0 + r1) * DIM + col);
    float4* xr0 = (float4*)(xr + (size_t)(row0 + r0) * DIM + col);
    float4* xr1 = (float4*)(xr + (size_t)(row0 + r1) * DIM + col);
    #pragma unroll
    for (int j = 0; j < 4; j++) {
        float4 bL = blv[j], bR = brv[j];
        float4 o;
        o.x = aL0[4 * j + 0] + bL.x; o.y = aL0[4 * j + 1] + bL.y;
        o.z = aL0[4 * j + 2] + bL.z; o.w = aL0[4 * j + 3] + bL.w;
        xl0[j] = o;
        o.x = aL1[4 * j + 0] + bL.x; o.y = aL1[4 * j + 1] + bL.y;
        o.z = aL1[4 * j + 2] + bL.z; o.w = aL1[4 * j + 3] + bL.w;
        xl1[j] = o;
        o.x = aR0[4 * j + 0] + bR.x; o.y = aR0[4 * j + 1] + bR.y;
        o.z = aR0[4 * j + 2] + bR.z; o.w = aR0[4 * j + 3] + bR.w;
        xr0[j] = o;
        o.x = aR1[4 * j + 0] + bR.x; o.y = aR1[4 * j + 1] + bR.y;
        o.z = aR1[4 * j + 2] + bR.z; o.w = aR1[4 * j + 3] + bR.w;
        xr1[j] = o;
    }
}

// ---------------- GATv2 aggregation: warp per node, online softmax ----------------
__device__ __forceinline__ float leaky_dot(float4 v, float4 x, float4 w) {
    float ax = v.x + x.x, ay = v.y + x.y, az = v.z + x.z, aw = v.w + x.w;
    ax = ax > 0.f ? ax : NEG_SLOPE * ax;
    ay = ay > 0.f ? ay : NEG_SLOPE * ay;
    az = az > 0.f ? az : NEG_SLOPE * az;
    aw = aw > 0.f ? aw : NEG_SLOPE * aw;
    return ax * w.x + ay * w.y + az * w.z + aw * w.w;
}

__global__ __launch_bounds__(256) void k_gat(
    const float* __restrict__ xl, const float* __restrict__ xr,
    const float* __restrict__ att, const float* __restrict__ conv_bias,
    const float* __restrict__ bn_gamma, const float* __restrict__ bn_beta,
    const float* __restrict__ bn_mean, const float* __restrict__ bn_var,
    float* __restrict__ hout)
{
    int i = blockIdx.x * 8 + (threadIdx.x >> 5);
    if (i >= NODES) return;
    int lane = threadIdx.x & 31;
    int c = lane * 4;                    // feature offset; head = lane>>3

    float4 w   = *(const float4*)(att + c);
    float4 xr4 = *(const float4*)(xr + (size_t)i * DIM + c);

    // self loop seeds m / denom / acc
    float4 xls = *(const float4*)(xl + (size_t)i * DIM + c);
    float d = leaky_dot(xls, xr4, w);
    d += __shfl_xor_sync(0xffffffffu, d, 1);
    d += __shfl_xor_sync(0xffffffffu, d, 2);
    d += __shfl_xor_sync(0xffffffffu, d, 4);
    float m = d;
    float denom = 1.0f;
    float4 acc = xls;

    int beg = d_rowptr[i];
    int end = d_rowptr[i + 1];
    for (int j = beg; j < end; j++) {
        int src = d_srcs[j];
        float4 v = *(const float4*)(xl + (size_t)src * DIM + c);
        float dd = leaky_dot(v, xr4, w);
        dd += __shfl_xor_sync(0xffffffffu, dd, 1);
        dd += __shfl_xor_sync(0xffffffffu, dd, 2);
        dd += __shfl_xor_sync(0xffffffffu, dd, 4);
        float mn = fmaxf(m, dd);
        float cs = __expf(m - mn);
        float a = __expf(dd - mn);
        denom = denom * cs + a;
        acc.x = fmaf(acc.x, cs, a * v.x);
        acc.y = fmaf(acc.y, cs, a * v.y);
        acc.z = fmaf(acc.z, cs, a * v.z);
        acc.w = fmaf(acc.w, cs, a * v.w);
        m = mn;
    }

    float inv = 1.0f / denom;
    float4 bias = *(const float4*)(conv_bias + c);
    float4 ga = *(const float4*)(bn_gamma + c);
    float4 be = *(const float4*)(bn_beta + c);
    float4 mu = *(const float4*)(bn_mean + c);
    float4 va = *(const float4*)(bn_var + c);
    float4 o;
    o.x = fmaxf((acc.x * inv + bias.x - mu.x) * rsqrtf(va.x + BN_EPS) * ga.x + be.x, 0.f);
    o.y = fmaxf((acc.y * inv + bias.y - mu.y) * rsqrtf(va.y + BN_EPS) * ga.y + be.y, 0.f);
    o.z = fmaxf((acc.z * inv + bias.z - mu.z) * rsqrtf(va.z + BN_EPS) * ga.z + be.z, 0.f);
    o.w = fmaxf((acc.w * inv + bias.w - mu.w) * rsqrtf(va.w + BN_EPS) * ga.w + be.w, 0.f);
    *(float4*)(hout + (size_t)i * DIM + c) = o;
}

// ---------------- mean pool (batch sorted) + MLP 128->64->2 ----------------
__global__ void k_pool_mlp(
    const float* __restrict__ h, const int* __restrict__ batch,
    const float* __restrict__ W1, const float* __restrict__ b1,
    const float* __restrict__ W2, const float* __restrict__ b2,
    float* __restrict__ out)
{
    __shared__ float p[DIM];
    __shared__ float hid[64];
    int g = blockIdx.x;
    int t = threadIdx.x;   // 128

    int lo = 0, hi = NODES;
    while (lo < hi) { int mid = (lo + hi) >> 1; if (batch[mid] < g) lo = mid + 1; else hi = mid; }
    int beg = lo;
    hi = NODES;
    while (lo < hi) { int mid = (lo + hi) >> 1; if (batch[mid] < g + 1) lo = mid + 1; else hi = mid; }
    int end = lo;

    float sum = 0.f;
    for (int n = beg; n < end; n++) sum += h[(size_t)n * DIM + t];
    float cnt = (float)(end - beg);
    p[t] = sum / fmaxf(cnt, 1.0f);
    __syncthreads();

    if (t < 64) {
        float a = b1[t];
        #pragma unroll 8
        for (int k = 0; k < DIM; k++) a = fmaf(p[k], W1[k * 64 + t], a);
        hid[t] = fmaxf(a, 0.f);
    }
    __syncthreads();

    if (t < 2) {
        float a = b2[t];
        #pragma unroll 8
        for (int k = 0; k < 64; k++) a = fmaf(hid[k], W2[k * 2 + t], a);
        out[g * 2 + t] = a;
    }
}

// ---------------- launch ----------------
extern "C" void kernel_launch(void* const* d_in, const int* in_sizes, int n_in,
                              void* d_out, int out_size)
{
    const float* x     = (const float*)d_in[0];
    const int*   ei    = (const int*)d_in[1];
    const int*   batch = (const int*)d_in[2];
    const float* Wl    = (const float*)d_in[3];
    const float* bl    = (const float*)d_in[4];
    const float* Wr    = (const float*)d_in[5];
    const float* br    = (const float*)d_in[6];
    const float* att   = (const float*)d_in[7];
    const float* cb    = (const float*)d_in[8];
    const float* bng   = (const float*)d_in[9];
    const float* bnb   = (const float*)d_in[10];
    const float* bnm   = (const float*)d_in[11];
    const float* bnv   = (const float*)d_in[12];
    const float* W1    = (const float*)d_in[13];
    const float* b1    = (const float*)d_in[14];
    const float* W2    = (const float*)d_in[15];
    const float* b2    = (const float*)d_in[16];
    float* out = (float*)d_out;

    float *h0, *h1, *xl, *xr;
    cudaGetSymbolAddress((void**)&h0, d_h0);
    cudaGetSymbolAddress((void**)&h1, d_h1);
    cudaGetSymbolAddress((void**)&xl, d_xl);
    cudaGetSymbolAddress((void**)&xr, d_xr);

    // CSR by dst (once; reused by all 3 layers)
    k_zero_deg<<<(NODES + 255) / 256, 256>>>();
    k_hist<<<(EDGES + 255) / 256, 256>>>(ei);
    k_scan<<<1, 1024>>>();
    k_scatter<<<(EDGES + 255) / 256, 256>>>(ei);

    const float* hins[3]  = {x, h0, h1};
    float*       houts[3] = {h0, h1, h0};
    for (int l = 0; l < 3; l++) {
        k_gemm_dual<<<NODES / 64, 256>>>(hins[l],
                                         Wl + (size_t)l * DIM * DIM, bl + l * DIM,
                                         Wr + (size_t)l * DIM * DIM, br + l * DIM,
                                         xl, xr);
        k_gat<<<NODES / 8, 256>>>(xl, xr,
                                  att + l * DIM, cb + l * DIM,
                                  bng + l * DIM, bnb + l * DIM,
                                  bnm + l * DIM, bnv + l * DIM,
                                  houts[l]);
    }

    k_pool_mlp<<<GRAPHS, 128>>>(h0, batch, W1, b1, W2, b2, out);
}

// round 3
// speedup vs baseline: 3.5819x; 3.5819x over previous
#include <cuda_runtime.h>
#include <cuda_bf16.h>
#include <cstdint>

#define NODES 40000
#define EDGES 640000
#define DIM 128
#define GRAPHS 512
#define NEG_SLOPE 0.2f
#define BN_EPS 1e-5f

// ---------------- scratch (no allocations allowed) ----------------
__device__ float d_h0[NODES * DIM];
__device__ float d_xl[NODES * DIM];
__device__ float d_xr[NODES * DIM];
__device__ __nv_bfloat16 d_hhi[NODES * DIM];
__device__ __nv_bfloat16 d_hlo[NODES * DIM];
__device__ __nv_bfloat16 d_whi[3 * 2 * DIM * DIM];  // [L][2(l,r)][k=128][n=128] (natural layout)
__device__ __nv_bfloat16 d_wlo[3 * 2 * DIM * DIM];
__device__ int d_deg[NODES];
__device__ int d_rowptr[NODES + 1];
__device__ int d_cursor[NODES];
__device__ int d_srcs[EDGES];

__device__ __forceinline__ uint32_t smem_u32(const void* p) {
    uint32_t a;
    asm("{ .reg .u64 t; cvta.to.shared.u64 t, %1; cvt.u32.u64 %0, t; }" : "=r"(a) : "l"(p));
    return a;
}
__device__ __forceinline__ void ldsm_x4(uint32_t* r, uint32_t addr) {
    asm volatile("ldmatrix.sync.aligned.m8n8.x4.shared.b16 {%0,%1,%2,%3}, [%4];"
                 : "=r"(r[0]), "=r"(r[1]), "=r"(r[2]), "=r"(r[3]) : "r"(addr));
}
__device__ __forceinline__ void ldsm_x4_t(uint32_t* r, uint32_t addr) {
    asm volatile("ldmatrix.sync.aligned.m8n8.x4.trans.shared.b16 {%0,%1,%2,%3}, [%4];"
                 : "=r"(r[0]), "=r"(r[1]), "=r"(r[2]), "=r"(r[3]) : "r"(addr));
}
__device__ __forceinline__ void mma16816(float* c, const uint32_t* a, const uint32_t* b) {
    asm volatile(
        "mma.sync.aligned.m16n8k16.row.col.f32.bf16.bf16.f32 "
        "{%0,%1,%2,%3}, {%4,%5,%6,%7}, {%8,%9}, {%0,%1,%2,%3};"
        : "+f"(c[0]), "+f"(c[1]), "+f"(c[2]), "+f"(c[3])
        : "r"(a[0]), "r"(a[1]), "r"(a[2]), "r"(a[3]), "r"(b[0]), "r"(b[1]));
}

// ---------------- CSR build ----------------
__global__ void k_zero_deg() {
    int i = blockIdx.x * blockDim.x + threadIdx.x;
    if (i < NODES) d_deg[i] = 0;
}
__global__ void k_hist(const int* __restrict__ ei) {
    int e = blockIdx.x * blockDim.x + threadIdx.x;
    if (e < EDGES) atomicAdd(&d_deg[ei[EDGES + e]], 1);
}
__global__ void k_scan() {
    __shared__ int ws[32];
    __shared__ int s_carry;
    __shared__ int s_total;
    int tid = threadIdx.x, lane = tid & 31, wid = tid >> 5;
    if (tid == 0) s_carry = 0;
    __syncthreads();
    for (int base = 0; base < NODES; base += 1024) {
        int i = base + tid;
        int v = (i < NODES) ? d_deg[i] : 0;
        int x = v;
        #pragma unroll
        for (int o = 1; o < 32; o <<= 1) {
            int y = __shfl_up_sync(0xffffffffu, x, o);
            if (lane >= o) x += y;
        }
        if (lane == 31) ws[wid] = x;
        __syncthreads();
        if (wid == 0) {
            int sv = ws[lane], sx = sv;
            #pragma unroll
            for (int o = 1; o < 32; o <<= 1) {
                int y = __shfl_up_sync(0xffffffffu, sx, o);
                if (lane >= o) sx += y;
            }
            ws[lane] = sx - sv;
            if (lane == 31) s_total = sx;
        }
        __syncthreads();
        int excl = s_carry + ws[wid] + x - v;
        if (i < NODES) { d_rowptr[i] = excl; d_cursor[i] = excl; }
        __syncthreads();
        if (tid == 0) s_carry += s_total;
        __syncthreads();
    }
    if (threadIdx.x == 0) d_rowptr[NODES] = s_carry;
}
__global__ void k_scatter(const int* __restrict__ ei) {
    int e = blockIdx.x * blockDim.x + threadIdx.x;
    if (e < EDGES) {
        int dst = ei[EDGES + e];
        int pos = atomicAdd(&d_cursor[dst], 1);
        d_srcs[pos] = ei[e];
    }
}

// ---------------- fp32 -> bf16 hi/lo converts ----------------
__global__ void k_convert_x(const float* __restrict__ x) {
    int i = blockIdx.x * blockDim.x + threadIdx.x;
    if (i < NODES * DIM) {
        float v = x[i];
        __nv_bfloat16 h = __float2bfloat16(v);
        d_hhi[i] = h;
        d_hlo[i] = __float2bfloat16(v - __bfloat162float(h));
    }
}
__global__ void k_convert_w(const float* __restrict__ Wl, const float* __restrict__ Wr) {
    int l = blockIdx.x >> 1, m = blockIdx.x & 1;
    const float* W = (m ? Wr : Wl) + (size_t)l * DIM * DIM;
    __nv_bfloat16* oh = d_whi + (size_t)(l * 2 + m) * DIM * DIM;
    __nv_bfloat16* ol = d_wlo + (size_t)(l * 2 + m) * DIM * DIM;
    for (int t = threadIdx.x; t < DIM * DIM; t += blockDim.x) {
        float v = W[t];
        __nv_bfloat16 h = __float2bfloat16(v);
        oh[t] = h;
        ol[t] = __float2bfloat16(v - __bfloat162float(h));
    }
}

// ---------------- HMMA dual GEMM (bf16x3 emulated fp32) ----------------
// CTA: 128 rows x 128 cols, K=128 in one shot. blockIdx.y selects (Wl,bl,xl)/(Wr,br,xr).
// smem: A hi/lo [128m][128k], W hi/lo [128k][128n]; 16B chunks XOR-swizzled by (row&7).
#define SA_HI 0
#define SA_LO 32768
#define SW_HI 65536
#define SW_LO 98304
#define GSMEM 131072

__global__ __launch_bounds__(256, 1) void k_gemm_tc(
    const __nv_bfloat16* __restrict__ Ahi, const __nv_bfloat16* __restrict__ Alo,
    const __nv_bfloat16* __restrict__ Whi, const __nv_bfloat16* __restrict__ Wlo,  // [2][128][128]
    const float* __restrict__ bl, const float* __restrict__ br,
    float* __restrict__ xl, float* __restrict__ xr)
{
    extern __shared__ char smem[];
    uint32_t sb = smem_u32(smem);
    int tid = threadIdx.x;
    int row0 = blockIdx.x * 128;
    int mat = blockIdx.y;

    const float* bias = mat ? br : bl;
    float* out = mat ? d_xr : d_xl;
    const uint4* ahi4 = (const uint4*)Ahi;
    const uint4* alo4 = (const uint4*)Alo;
    const uint4* wh4 = (const uint4*)(Whi + (size_t)mat * DIM * DIM);
    const uint4* wl4 = (const uint4*)(Wlo + (size_t)mat * DIM * DIM);

    for (int t = tid; t < 2048; t += 256) {
        int r = t >> 4, c = t & 15;
        int so = r * 256 + (((c ^ (r & 7))) << 4);
        int grow = row0 + r;
        if (grow > NODES - 1) grow = NODES - 1;
        *(uint4*)(smem + SA_HI + so) = ahi4[grow * 16 + c];
        *(uint4*)(smem + SA_LO + so) = alo4[grow * 16 + c];
        *(uint4*)(smem + SW_HI + so) = wh4[t];
        *(uint4*)(smem + SW_LO + so) = wl4[t];
    }
    __syncthreads();

    int w = tid >> 5, lane = tid & 31;
    int mBase = (w >> 2) * 64;   // warp row group (2)
    int nBase = (w & 3) * 32;    // warp col group (4)

    float acc[4][4][4];
    #pragma unroll
    for (int mt = 0; mt < 4; mt++)
        #pragma unroll
        for (int nt = 0; nt < 4; nt++)
            #pragma unroll
            for (int j = 0; j < 4; j++) acc[mt][nt][j] = 0.f;

    int arow = lane & 15;
    int asel = lane >> 4;                       // chunk +0/+1 (k halves)
    int brow_in = (lane & 7) + ((lane >> 3) & 1) * 8;
    int bsel = lane >> 4;                       // n +0/+8

    #pragma unroll
    for (int ks = 0; ks < 8; ks++) {
        uint32_t ah[4][4], al[4][4];
        int achunk = ks * 2 + asel;
        #pragma unroll
        for (int mt = 0; mt < 4; mt++) {
            int r = mBase + mt * 16 + arow;
            uint32_t off = r * 256 + ((achunk ^ (r & 7)) << 4);
            ldsm_x4(ah[mt], sb + SA_HI + off);
            ldsm_x4(al[mt], sb + SA_LO + off);
        }
        uint32_t bh[2][4], bo[2][4];
        int brow = ks * 16 + brow_in;
        #pragma unroll
        for (int nt2 = 0; nt2 < 2; nt2++) {
            int chunk = ((nBase + nt2 * 16) >> 3) + bsel;
            uint32_t off = brow * 256 + ((chunk ^ (brow & 7)) << 4);
            ldsm_x4_t(bh[nt2], sb + SW_HI + off);
            ldsm_x4_t(bo[nt2], sb + SW_LO + off);
        }
        #pragma unroll
        for (int mt = 0; mt < 4; mt++)
            #pragma unroll
            for (int nt = 0; nt < 4; nt++) {
                const uint32_t* ph = &bh[nt >> 1][(nt & 1) * 2];
                const uint32_t* pl = &bo[nt >> 1][(nt & 1) * 2];
                mma16816(acc[mt][nt], ah[mt], ph);   // hi*hi
                mma16816(acc[mt][nt], al[mt], ph);   // lo*hi
                mma16816(acc[mt][nt], ah[mt], pl);   // hi*lo
            }
    }

    // epilogue: + bias, direct stores
    int r0 = lane >> 2;
    int c2 = (lane & 3) * 2;
    #pragma unroll
    for (int nt = 0; nt < 4; nt++) {
        int col = nBase + nt * 8 + c2;
        float2 bi = *(const float2*)(bias + col);
        #pragma unroll
        for (int mt = 0; mt < 4; mt++) {
            int g0 = row0 + mBase + mt * 16 + r0;
            if (g0 < NODES) {
                float2 o = {acc[mt][nt][0] + bi.x, acc[mt][nt][1] + bi.y};
                *(float2*)(out + (size_t)g0 * DIM + col) = o;
            }
            int g1 = g0 + 8;
            if (g1 < NODES) {
                float2 o = {acc[mt][nt][2] + bi.x, acc[mt][nt][3] + bi.y};
                *(float2*)(out + (size_t)g1 * DIM + col) = o;
            }
        }
    }
    (void)xl; (void)xr;
}

// ---------------- GATv2 aggregation: warp per node, online softmax ----------------
__device__ __forceinline__ float leaky_dot(float4 v, float4 x, float4 w) {
    float ax = v.x + x.x, ay = v.y + x.y, az = v.z + x.z, aw = v.w + x.w;
    ax = ax > 0.f ? ax : NEG_SLOPE * ax;
    ay = ay > 0.f ? ay : NEG_SLOPE * ay;
    az = az > 0.f ? az : NEG_SLOPE * az;
    aw = aw > 0.f ? aw : NEG_SLOPE * aw;
    return ax * w.x + ay * w.y + az * w.z + aw * w.w;
}

__global__ __launch_bounds__(256) void k_gat(
    const float* __restrict__ xl, const float* __restrict__ xr,
    const float* __restrict__ att, const float* __restrict__ conv_bias,
    const float* __restrict__ bn_gamma, const float* __restrict__ bn_beta,
    const float* __restrict__ bn_mean, const float* __restrict__ bn_var,
    float* __restrict__ hout, int write_bf, int write_f32)
{
    int i = blockIdx.x * 8 + (threadIdx.x >> 5);
    if (i >= NODES) return;
    int lane = threadIdx.x & 31;
    int c = lane * 4;

    float4 w   = *(const float4*)(att + c);
    float4 xr4 = *(const float4*)(xr + (size_t)i * DIM + c);

    float4 xls = *(const float4*)(xl + (size_t)i * DIM + c);
    float d = leaky_dot(xls, xr4, w);
    d += __shfl_xor_sync(0xffffffffu, d, 1);
    d += __shfl_xor_sync(0xffffffffu, d, 2);
    d += __shfl_xor_sync(0xffffffffu, d, 4);
    float m = d;
    float denom = 1.0f;
    float4 acc = xls;

    int beg = d_rowptr[i];
    int end = d_rowptr[i + 1];
    if (beg < end) {
        int src = d_srcs[beg];
        float4 v = *(const float4*)(xl + (size_t)src * DIM + c);
        for (int j = beg; j < end; j++) {
            float4 cur = v;
            if (j + 1 < end) {                       // prefetch next gather
                int sn = d_srcs[j + 1];
                v = *(const float4*)(xl + (size_t)sn * DIM + c);
            }
            float dd = leaky_dot(cur, xr4, w);
            dd += __shfl_xor_sync(0xffffffffu, dd, 1);
            dd += __shfl_xor_sync(0xffffffffu, dd, 2);
            dd += __shfl_xor_sync(0xffffffffu, dd, 4);
            float mn = fmaxf(m, dd);
            float cs = __expf(m - mn);
            float a = __expf(dd - mn);
            denom = denom * cs + a;
            acc.x = fmaf(acc.x, cs, a * cur.x);
            acc.y = fmaf(acc.y, cs, a * cur.y);
            acc.z = fmaf(acc.z, cs, a * cur.z);
            acc.w = fmaf(acc.w, cs, a * cur.w);
            m = mn;
        }
    }

    float inv = 1.0f / denom;
    float4 bias = *(const float4*)(conv_bias + c);
    float4 ga = *(const float4*)(bn_gamma + c);
    float4 be = *(const float4*)(bn_beta + c);
    float4 mu = *(const float4*)(bn_mean + c);
    float4 va = *(const float4*)(bn_var + c);
    float4 o;
    o.x = fmaxf((acc.x * inv + bias.x - mu.x) * rsqrtf(va.x + BN_EPS) * ga.x + be.x, 0.f);
    o.y = fmaxf((acc.y * inv + bias.y - mu.y) * rsqrtf(va.y + BN_EPS) * ga.y + be.y, 0.f);
    o.z = fmaxf((acc.z * inv + bias.z - mu.z) * rsqrtf(va.z + BN_EPS) * ga.z + be.z, 0.f);
    o.w = fmaxf((acc.w * inv + bias.w - mu.w) * rsqrtf(va.w + BN_EPS) * ga.w + be.w, 0.f);

    if (write_f32) *(float4*)(hout + (size_t)i * DIM + c) = o;
    if (write_bf) {
        __nv_bfloat16 hx = __float2bfloat16(o.x);
        __nv_bfloat16 hy = __float2bfloat16(o.y);
        __nv_bfloat16 hz = __float2bfloat16(o.z);
        __nv_bfloat16 hw = __float2bfloat16(o.w);
        __nv_bfloat162* ph = (__nv_bfloat162*)(d_hhi + (size_t)i * DIM + c);
        ph[0] = __nv_bfloat162(hx, hy);
        ph[1] = __nv_bfloat162(hz, hw);
        __nv_bfloat162* pl = (__nv_bfloat162*)(d_hlo + (size_t)i * DIM + c);
        pl[0] = __nv_bfloat162(__float2bfloat16(o.x - __bfloat162float(hx)),
                               __float2bfloat16(o.y - __bfloat162float(hy)));
        pl[1] = __nv_bfloat162(__float2bfloat16(o.z - __bfloat162float(hz)),
                               __float2bfloat16(o.w - __bfloat162float(hw)));
    }
}

// ---------------- mean pool (batch sorted) + MLP 128->64->2 ----------------
__global__ void k_pool_mlp(
    const float* __restrict__ h, const int* __restrict__ batch,
    const float* __restrict__ W1, const float* __restrict__ b1,
    const float* __restrict__ W2, const float* __restrict__ b2,
    float* __restrict__ out)
{
    __shared__ float p[DIM];
    __shared__ float hid[64];
    int g = blockIdx.x;
    int t = threadIdx.x;

    int lo = 0, hi = NODES;
    while (lo < hi) { int mid = (lo + hi) >> 1; if (batch[mid] < g) lo = mid + 1; else hi = mid; }
    int beg = lo;
    hi = NODES;
    while (lo < hi) { int mid = (lo + hi) >> 1; if (batch[mid] < g + 1) lo = mid + 1; else hi = mid; }
    int end = lo;

    float sum = 0.f;
    for (int n = beg; n < end; n++) sum += h[(size_t)n * DIM + t];
    float cnt = (float)(end - beg);
    p[t] = sum / fmaxf(cnt, 1.0f);
    __syncthreads();

    if (t < 64) {
        float a = b1[t];
        #pragma unroll 8
        for (int k = 0; k < DIM; k++) a = fmaf(p[k], W1[k * 64 + t], a);
        hid[t] = fmaxf(a, 0.f);
    }
    __syncthreads();

    if (t < 2) {
        float a = b2[t];
        #pragma unroll 8
        for (int k = 0; k < 64; k++) a = fmaf(hid[k], W2[k * 2 + t], a);
        out[g * 2 + t] = a;
    }
}

// ---------------- launch ----------------
extern "C" void kernel_launch(void* const* d_in, const int* in_sizes, int n_in,
                              void* d_out, int out_size)
{
    const float* x     = (const float*)d_in[0];
    const int*   ei    = (const int*)d_in[1];
    const int*   batch = (const int*)d_in[2];
    const float* Wl    = (const float*)d_in[3];
    const float* bl    = (const float*)d_in[4];
    const float* Wr    = (const float*)d_in[5];
    const float* br    = (const float*)d_in[6];
    const float* att   = (const float*)d_in[7];
    const float* cb    = (const float*)d_in[8];
    const float* bng   = (const float*)d_in[9];
    const float* bnb   = (const float*)d_in[10];
    const float* bnm   = (const float*)d_in[11];
    const float* bnv   = (const float*)d_in[12];
    const float* W1    = (const float*)d_in[13];
    const float* b1    = (const float*)d_in[14];
    const float* W2    = (const float*)d_in[15];
    const float* b2    = (const float*)d_in[16];
    float* out = (float*)d_out;

    float *h0, *xl, *xr;
    __nv_bfloat16 *hhi, *hlo, *whi, *wlo;
    cudaGetSymbolAddress((void**)&h0, d_h0);
    cudaGetSymbolAddress((void**)&xl, d_xl);
    cudaGetSymbolAddress((void**)&xr, d_xr);
    cudaGetSymbolAddress((void**)&hhi, d_hhi);
    cudaGetSymbolAddress((void**)&hlo, d_hlo);
    cudaGetSymbolAddress((void**)&whi, d_whi);
    cudaGetSymbolAddress((void**)&wlo, d_wlo);

    static int smem_set = 0;
    if (!smem_set) {
        cudaFuncSetAttribute(k_gemm_tc, cudaFuncAttributeMaxDynamicSharedMemorySize, GSMEM);
        smem_set = 1;
    }

    // CSR by dst (once; reused by all 3 layers)
    k_zero_deg<<<(NODES + 255) / 256, 256>>>();
    k_hist<<<(EDGES + 255) / 256, 256>>>(ei);
    k_scan<<<1, 1024>>>();
    k_scatter<<<(EDGES + 255) / 256, 256>>>(ei);

    // bf16 hi/lo conversions
    k_convert_x<<<(NODES * DIM + 255) / 256, 256>>>(x);
    k_convert_w<<<6, 256>>>(Wl, Wr);

    dim3 ggrid((NODES + 127) / 128, 2);
    for (int l = 0; l < 3; l++) {
        k_gemm_tc<<<ggrid, 256, GSMEM>>>(
            hhi, hlo,
            whi + (size_t)l * 2 * DIM * DIM, wlo + (size_t)l * 2 * DIM * DIM,
            bl + l * DIM, br + l * DIM, xl, xr);
        k_gat<<<NODES / 8, 256>>>(xl, xr,
                                  att + l * DIM, cb + l * DIM,
                                  bng + l * DIM, bnb + l * DIM,
                                  bnm + l * DIM, bnv + l * DIM,
                                  h0, (l < 2) ? 1 : 0, (l == 2) ? 1 : 0);
    }

    k_pool_mlp<<<GRAPHS, 128>>>(h0, batch, W1, b1, W2, b2, out);
}